// round 1
// baseline (speedup 1.0000x reference)
#include <cuda_runtime.h>
#include <cstdint>
#include <cstddef>

// ---------------------------------------------------------------------------
// CBFNet on GB300: compact dead edges -> fused-gather SGEMM (f32x2) edge MLP
// -> gated segment softmax (folded normalization, vector RED) -> agent MLP.
// ---------------------------------------------------------------------------

#define MAXE 800000
#define MAXN 50000

typedef unsigned long long ull;

// Scratch (allocation-free rule: __device__ globals)
__device__ float    g_H[(size_t)MAXE * 256];
__device__ float    g_MSG[(size_t)MAXE * 128];
__device__ float    g_logits[MAXE];
__device__ int      g_eidx[MAXE];
__device__ int      g_rcvc[MAXE];
__device__ unsigned g_segmax[MAXN];
__device__ float    g_denom[MAXN];
__device__ float    g_aggr[(size_t)MAXN * 128];
__device__ float    g_X0[(size_t)MAXN * 128];
__device__ float    g_X1[(size_t)MAXN * 256];
__device__ float    g_X2[(size_t)MAXN * 256];
__device__ int      g_count[1];

// ---- f32x2 helpers (Blackwell paired FP32 pipe) ----
__device__ __forceinline__ ull pk2(float a) {
    ull r; unsigned u = __float_as_uint(a);
    asm("mov.b64 %0, {%1, %2};" : "=l"(r) : "r"(u), "r"(u));
    return r;
}
__device__ __forceinline__ ull pkp(float x, float y) {
    ull r;
    asm("mov.b64 %0, {%1, %2};" : "=l"(r)
        : "r"(__float_as_uint(x)), "r"(__float_as_uint(y)));
    return r;
}
__device__ __forceinline__ void fma2(ull& d, ull a, ull b) {
    asm("fma.rn.f32x2 %0, %1, %2, %0;" : "+l"(d) : "l"(a), "l"(b));
}
__device__ __forceinline__ float2 upk(ull v) {
    float2 r;
    asm("mov.b64 {%0, %1}, %2;" : "=f"(r.x), "=f"(r.y) : "l"(v));
    return r;
}

// ---- monotone float<->uint mapping for atomicMax on floats ----
__device__ __forceinline__ unsigned fmap(float f) {
    unsigned u = __float_as_uint(f);
    return (u & 0x80000000u) ? ~u : (u | 0x80000000u);
}
__device__ __forceinline__ float funmap(unsigned u) {
    return __uint_as_float((u & 0x80000000u) ? (u ^ 0x80000000u) : ~u);
}

// ---------------------------------------------------------------------------
// Tiled SGEMM: C[M,NT] = act(A[M,KD] @ B[KD,NT] + bias), M read from device.
// GATHER mode builds A rows on the fly from node/edge features via g_eidx.
// BM=BN=128, BK=16, 256 threads, 8x8 microtile, f32x2 accumulators (pairs
// along N), double-buffered smem with register-staged prefetch.
// ---------------------------------------------------------------------------
#define BM 128
#define BN 128
#define BK 16

template<int KD, int NT, bool GATHER, bool RELU>
__global__ __launch_bounds__(256, 2)
void gemm_k(const float* __restrict__ A,
            const float* __restrict__ nodef,
            const float* __restrict__ edgef,
            const int*   __restrict__ senders,
            const int*   __restrict__ receivers,
            const float* __restrict__ B,
            const float* __restrict__ bias,
            float*       __restrict__ C,
            const int*   __restrict__ mptr)
{
    const int M = *mptr;
    const int row0 = blockIdx.x * BM;
    if (row0 >= M) return;
    const int n0  = blockIdx.y * BN;
    const int tid = threadIdx.x;

    __shared__ float As[2][BK][BM];
    __shared__ float Bs[2][BK][BN];
    __shared__ int sS[BM], sR[BM], sE[BM];

    if (GATHER) {
        if (tid < BM) {
            int m = row0 + tid;
            int e = g_eidx[(m < M) ? m : 0];
            sE[tid] = e;
            sS[tid] = senders[e];
            sR[tid] = receivers[e];
        }
        __syncthreads();
    }

    // A-load mapping: thread -> row a_m, k-offsets a_k0 + {0,4}
    const int a_m  = tid >> 1;
    const int a_k0 = (tid & 1) * 8;
    // B-load mapping: thread -> k b_k, col offsets b_n + {0,4}
    const int b_k  = tid >> 4;
    const int b_n  = (tid & 15) * 8;

    float4 ra[2], rb[2];

    auto loadA = [&](int kb) {
        #pragma unroll
        for (int i = 0; i < 2; ++i) {
            int k   = kb * BK + a_k0 + i * 4;
            int row = row0 + a_m;
            float4 v = make_float4(0.f, 0.f, 0.f, 0.f);
            if (row < M) {
                if (GATHER) {
                    if (k < 64)       v = *(const float4*)(nodef + (size_t)sS[a_m] * 64 + k);
                    else if (k < 128) v = *(const float4*)(nodef + (size_t)sR[a_m] * 64 + (k - 64));
                    else              v = *(const float4*)(edgef + (size_t)sE[a_m] * 32 + (k - 128));
                } else {
                    v = *(const float4*)(A + (size_t)row * KD + k);
                }
            }
            ra[i] = v;
        }
    };
    auto loadB = [&](int kb) {
        #pragma unroll
        for (int i = 0; i < 2; ++i) {
            int k = kb * BK + b_k;
            rb[i] = *(const float4*)(B + (size_t)k * NT + n0 + b_n + i * 4);
        }
    };
    auto stash = [&](int b) {
        #pragma unroll
        for (int i = 0; i < 2; ++i) {
            int kl = a_k0 + i * 4;
            As[b][kl    ][a_m] = ra[i].x;
            As[b][kl + 1][a_m] = ra[i].y;
            As[b][kl + 2][a_m] = ra[i].z;
            As[b][kl + 3][a_m] = ra[i].w;
            *(float4*)&Bs[b][b_k][b_n + i * 4] = rb[i];
        }
    };

    loadA(0); loadB(0);
    stash(0);
    __syncthreads();

    ull acc[8][4] = {};
    const int my = (tid >> 4) * 8;
    const int nx = (tid & 15) * 8;
    constexpr int NKB = KD / BK;
    int buf = 0;

    #pragma unroll 1
    for (int kb = 0; kb < NKB; ++kb) {
        if (kb + 1 < NKB) { loadA(kb + 1); loadB(kb + 1); }
        #pragma unroll
        for (int k = 0; k < BK; ++k) {
            float4 A0 = *(const float4*)&As[buf][k][my];
            float4 A1 = *(const float4*)&As[buf][k][my + 4];
            float4 B0 = *(const float4*)&Bs[buf][k][nx];
            float4 B1 = *(const float4*)&Bs[buf][k][nx + 4];
            ull bb0 = pkp(B0.x, B0.y), bb1 = pkp(B0.z, B0.w);
            ull bb2 = pkp(B1.x, B1.y), bb3 = pkp(B1.z, B1.w);
            float av[8] = {A0.x, A0.y, A0.z, A0.w, A1.x, A1.y, A1.z, A1.w};
            #pragma unroll
            for (int r = 0; r < 8; ++r) {
                ull ar = pk2(av[r]);
                fma2(acc[r][0], ar, bb0);
                fma2(acc[r][1], ar, bb1);
                fma2(acc[r][2], ar, bb2);
                fma2(acc[r][3], ar, bb3);
            }
        }
        if (kb + 1 < NKB) {
            stash(buf ^ 1);
            __syncthreads();
            buf ^= 1;
        }
    }

    float bv[8];
    #pragma unroll
    for (int j = 0; j < 8; ++j) bv[j] = bias[n0 + nx + j];

    #pragma unroll
    for (int r = 0; r < 8; ++r) {
        int row = row0 + my + r;
        if (row < M) {
            float o[8];
            #pragma unroll
            for (int c = 0; c < 4; ++c) {
                float2 v = upk(acc[r][c]);
                o[2 * c]     = v.x + bv[2 * c];
                o[2 * c + 1] = v.y + bv[2 * c + 1];
            }
            if (RELU) {
                #pragma unroll
                for (int j = 0; j < 8; ++j) o[j] = fmaxf(o[j], 0.f);
            }
            float* cp = C + (size_t)row * NT + n0 + nx;
            *(float4*)cp       = make_float4(o[0], o[1], o[2], o[3]);
            *(float4*)(cp + 4) = make_float4(o[4], o[5], o[6], o[7]);
        }
    }
}

// ---------------------------------------------------------------------------
// Small kernels
// ---------------------------------------------------------------------------
__global__ void init_k(int n_nodes) {
    int i = blockIdx.x * blockDim.x + threadIdx.x;
    if (i < n_nodes * 128) g_aggr[i] = 0.f;
    if (i < n_nodes) { g_denom[i] = 0.f; g_segmax[i] = 0u; }
    if (i == 0) g_count[0] = 0;
}

// Keep only edges whose receiver < n_agents (others can't affect the output).
__global__ void compact_k(const int* __restrict__ receivers,
                          const int* __restrict__ nag, int n_edges) {
    int e = blockIdx.x * blockDim.x + threadIdx.x;
    if (e >= n_edges) return;
    int r = receivers[e];
    if (r < *nag) {
        int p = atomicAdd(g_count, 1);
        g_eidx[p] = e;
        g_rcvc[p] = r;
    }
}

// logit = msg . w_gate + b_gate ; atomicMax into per-receiver max.
__global__ void logits_k(const float* __restrict__ w_gate,
                         const float* __restrict__ b_gate) {
    int idx  = blockIdx.x * blockDim.x + threadIdx.x;
    int row  = idx >> 5, lane = idx & 31;
    if (row >= g_count[0]) return;
    float4 m4 = *(const float4*)(g_MSG + (size_t)row * 128 + lane * 4);
    float4 g4 = *(const float4*)(w_gate + lane * 4);
    float s = m4.x * g4.x + m4.y * g4.y + m4.z * g4.z + m4.w * g4.w;
    #pragma unroll
    for (int o = 16; o; o >>= 1) s += __shfl_xor_sync(0xffffffffu, s, o);
    if (lane == 0) {
        float lg = s + b_gate[0];
        g_logits[row] = lg;
        atomicMax(&g_segmax[g_rcvc[row]], fmap(lg));
    }
}

// w = exp(logit - segmax); denom += w; aggr += w * msg (vector RED).
// Normalization by denom is folded into norm_k (softmax algebra).
__global__ void aggr_k() {
    int idx = blockIdx.x * blockDim.x + threadIdx.x;
    int row = idx >> 5, lane = idx & 31;
    if (row >= g_count[0]) return;
    int rv = g_rcvc[row];
    float w = expf(g_logits[row] - funmap(g_segmax[rv]));
    if (lane == 0) atomicAdd(&g_denom[rv], w);
    float4 m4 = *(const float4*)(g_MSG + (size_t)row * 128 + lane * 4);
    float* dst = g_aggr + (size_t)rv * 128 + lane * 4;
    asm volatile("red.global.add.v4.f32 [%0], {%1, %2, %3, %4};"
                 :: "l"(dst), "f"(m4.x * w), "f"(m4.y * w),
                    "f"(m4.z * w), "f"(m4.w * w)
                 : "memory");
}

__global__ void norm_k(const int* __restrict__ nag, int n_nodes) {
    int i = blockIdx.x * blockDim.x + threadIdx.x;
    if (i >= n_nodes * 128) return;
    int row = i >> 7;
    if (row < *nag) g_X0[i] = g_aggr[i] / (g_denom[row] + 1e-9f);
}

__global__ void out_k(const float* __restrict__ W, const float* __restrict__ b,
                      const int* __restrict__ nag, float* __restrict__ out) {
    int idx = blockIdx.x * blockDim.x + threadIdx.x;
    int row = idx >> 5, lane = idx & 31;
    if (row >= *nag) return;
    const float4* xr = (const float4*)(g_X2 + (size_t)row * 256);
    const float4* wr = (const float4*)W;
    float s = 0.f;
    #pragma unroll
    for (int j = 0; j < 2; ++j) {
        float4 x = xr[lane + 32 * j], wv = wr[lane + 32 * j];
        s += x.x * wv.x + x.y * wv.y + x.z * wv.z + x.w * wv.w;
    }
    #pragma unroll
    for (int o = 16; o; o >>= 1) s += __shfl_xor_sync(0xffffffffu, s, o);
    if (lane == 0) out[row] = tanhf(s + b[0]);
}

// ---------------------------------------------------------------------------
extern "C" void kernel_launch(void* const* d_in, const int* in_sizes, int n_in,
                              void* d_out, int out_size)
{
    const float* node_feats = (const float*)d_in[0];
    const float* edge_feats = (const float*)d_in[1];
    const float* W_msg1 = (const float*)d_in[2];
    const float* b_msg1 = (const float*)d_in[3];
    const float* W_msg2 = (const float*)d_in[4];
    const float* b_msg2 = (const float*)d_in[5];
    const float* w_gate = (const float*)d_in[6];
    const float* b_gate = (const float*)d_in[7];
    const float* W_h1   = (const float*)d_in[8];
    const float* b_h1   = (const float*)d_in[9];
    const float* W_h2   = (const float*)d_in[10];
    const float* b_h2   = (const float*)d_in[11];
    const float* W_out  = (const float*)d_in[12];
    const float* b_out  = (const float*)d_in[13];
    const int*   senders   = (const int*)d_in[14];
    const int*   receivers = (const int*)d_in[15];
    const int*   nag       = (const int*)d_in[16];
    float* out = (float*)d_out;

    int n_nodes = in_sizes[0] / 64;
    int n_edges = in_sizes[14];

    float *pH, *pMSG, *pX0, *pX1, *pX2;
    int *pcount;
    cudaGetSymbolAddress((void**)&pH,     g_H);
    cudaGetSymbolAddress((void**)&pMSG,   g_MSG);
    cudaGetSymbolAddress((void**)&pX0,    g_X0);
    cudaGetSymbolAddress((void**)&pX1,    g_X1);
    cudaGetSymbolAddress((void**)&pX2,    g_X2);
    cudaGetSymbolAddress((void**)&pcount, g_count);

    const int t = 256;
    init_k<<<(n_nodes * 128 + t - 1) / t, t>>>(n_nodes);
    compact_k<<<(n_edges + t - 1) / t, t>>>(receivers, nag, n_edges);

    // Edge MLP (compacted rows): [cnt,160]@[160,256] relu ; [cnt,256]@[256,128] relu
    dim3 g1((n_edges + BM - 1) / BM, 2);
    gemm_k<160, 256, true,  true><<<g1, 256>>>(nullptr, node_feats, edge_feats,
                                               senders, receivers,
                                               W_msg1, b_msg1, pH, pcount);
    dim3 g2((n_edges + BM - 1) / BM, 1);
    gemm_k<256, 128, false, true><<<g2, 256>>>(pH, nullptr, nullptr, nullptr, nullptr,
                                               W_msg2, b_msg2, pMSG, pcount);

    // Gated segment softmax aggregation
    logits_k<<<(n_edges * 32 + t - 1) / t, t>>>(w_gate, b_gate);
    aggr_k<<<(n_edges * 32 + t - 1) / t, t>>>();
    norm_k<<<(n_nodes * 128 + t - 1) / t, t>>>(nag, n_nodes);

    // Agent MLP: [na,128]@[128,256] relu ; [na,256]@[256,256] relu ; dot+tanh
    dim3 g3((n_nodes + BM - 1) / BM, 2);
    gemm_k<128, 256, false, true><<<g3, 256>>>(pX0, nullptr, nullptr, nullptr, nullptr,
                                               W_h1, b_h1, pX1, nag);
    gemm_k<256, 256, false, true><<<g3, 256>>>(pX1, nullptr, nullptr, nullptr, nullptr,
                                               W_h2, b_h2, pX2, nag);
    out_k<<<(n_nodes * 32 + t - 1) / t, t>>>(W_out, b_out, nag, out);
}